// round 14
// baseline (speedup 1.0000x reference)
#include <cuda_runtime.h>
#include <cstdint>

#define NPIX  1600
#define WIDTH 40
#define HID   64
#define TI    64
#define TJ    32
#define ST    68       // 272B rows: 16B-aligned for cp.async, conflict-free LDS.128
#define OT    36

typedef unsigned long long u64;

__device__ float g_U[NPIX][HID];
__device__ float g_V[NPIX][HID];

// ---- packed f32x2 helpers ----
static __device__ __forceinline__ u64 add2(u64 a, u64 b) {
    u64 r; asm("add.rn.f32x2 %0, %1, %2;" : "=l"(r) : "l"(a), "l"(b)); return r;
}
static __device__ __forceinline__ u64 fma2(u64 a, u64 b, u64 c) {
    u64 r; asm("fma.rn.f32x2 %0, %1, %2, %3;" : "=l"(r) : "l"(a), "l"(b), "l"(c)); return r;
}
static __device__ __forceinline__ float2 up2(u64 v) {
    float2 r; asm("mov.b64 {%0, %1}, %2;" : "=f"(r.x), "=f"(r.y) : "l"(v)); return r;
}
static __device__ __forceinline__ u64 pk2(float a, float b) {
    u64 r; asm("mov.b64 %0, {%1, %2};" : "=l"(r) : "f"(a), "f"(b)); return r;
}
static __device__ __forceinline__ u64 relu2(u64 v) {
    float2 t = up2(v);
    return pk2(fmaxf(t.x, 0.0f), fmaxf(t.y, 0.0f));
}
static __device__ __forceinline__ uint32_t s2u(const void* p) {
    return (uint32_t)__cvta_generic_to_shared(p);
}
static __device__ __forceinline__ void cpa16(uint32_t dst, const void* src) {
    asm volatile("cp.async.cg.shared.global [%0], [%1], 16;" :: "r"(dst), "l"(src));
}

// ---------------------------------------------------------------------------
// prep: 100 blocks x 128 threads, 16 pixels each. Signals PDL dependents
// immediately (their griddepcontrol.wait still blocks until we complete).
// ---------------------------------------------------------------------------
__global__ void __launch_bounds__(128) prep_kernel(
    const int* __restrict__ qmod_p, const int* __restrict__ kmod_p,
    const float* __restrict__ smap,      // (4,1,80,80)
    const float* __restrict__ memb,      // (3,16)
    const float* __restrict__ W1,        // (36,64)
    const float* __restrict__ b1)        // (64,)
{
    asm volatile("griddepcontrol.launch_dependents;");

    __shared__ float part[16][5];
    __shared__ float s_sh[16];
    __shared__ float mv[32];
    __shared__ float Cs[HID];

    const int tid = threadIdx.x;
    const int n0  = blockIdx.x * 16;
    const float raw[4] = {0.25f, 0.75f, 0.75f, 0.25f};

    if (tid >= 64 && tid < 96) {
        int t = tid - 64;
        int m = (t < 16) ? *qmod_p : *kmod_p;
        mv[t] = memb[m * 16 + (t & 15)];
    }

    if (tid < 64) {   // one (pixel,batch) per thread, 16 taps
        const int pix = tid >> 2, bb = tid & 3;
        const int n = n0 + pix;
        const int r = n / WIDTH, c = n % WIDTH;
        const float* base = smap + bb * 6400;
        float acc = 0.f;
        #pragma unroll
        for (int ty = 0; ty < 4; ty++) {
            int iy = 2 * r - 1 + ty;
            if (iy < 0 || iy >= 80) continue;
            #pragma unroll
            for (int tx = 0; tx < 4; tx++) {
                int ix = 2 * c - 1 + tx;
                if (ix < 0 || ix >= 80) continue;
                acc += raw[ty] * raw[tx] * base[iy * 80 + ix];
            }
        }
        part[pix][bb] = acc;
    }
    __syncthreads();

    if (tid < HID) {                      // C[h]
        float cc = b1[tid];
        #pragma unroll
        for (int k = 0; k < 32; k++)
            cc += mv[k] * W1[(2 + k) * HID + tid];
        Cs[tid] = cc;
    } else if (tid < 80) {                // finalize s (edge renorm, batch mean)
        const int p = tid - 64;
        const int n = n0 + p;
        const int r = n / WIDTH, c = n % WIDTH;
        float sy = 0.f, sx = 0.f;
        #pragma unroll
        for (int q = 0; q < 4; q++) {
            int iy = 2 * r - 1 + q; if (iy >= 0 && iy < 80) sy += raw[q];
            int ix = 2 * c - 1 + q; if (ix >= 0 && ix < 80) sx += raw[q];
        }
        s_sh[p] = (part[p][0] + part[p][1] + part[p][2] + part[p][3])
                  / (sy * sx) * 0.25f;
    }
    __syncthreads();

    {   // U and V rows (h-coalesced), 8 n's per thread
        const int hh = tid & 63, ng = tid >> 6;
        const float w0  = W1[hh];
        const float w1  = W1[HID + hh];
        const float wsi = W1[34 * HID + hh];
        const float wsj = W1[35 * HID + hh];
        const float ch  = Cs[hh];
        #pragma unroll
        for (int k = 0; k < 8; k++) {
            int nn = ng * 8 + k;
            int n = n0 + nn;
            int r = n / WIDTH, c = n % WIDTH;
            float x = (float)c * (1.0f / 39.0f) - 0.5f;
            float y = (float)r * (1.0f / 39.0f) - 0.5f;
            float s = s_sh[nn];
            float xy = x * w0 + y * w1;
            g_U[n][hh] =  xy + s * wsi + ch;
            g_V[n][hh] = -xy + s * wsj;
        }
    }
}

// ---------------------------------------------------------------------------
// main: R7/R13-proven body. PDL: preamble (w2/b2 loads, indices) overlaps
// prep; griddepcontrol.wait gates only the g_U/g_V staging.
// ---------------------------------------------------------------------------
__global__ void __launch_bounds__(128, 7) rpe_main_kernel(
    float* __restrict__ out,
    const float* __restrict__ W2,    // (64,)
    const float* __restrict__ b2)    // (1,)
{
    __shared__ float Us[TI * ST];
    __shared__ float Vs[TJ * ST];
    __shared__ float w2s[HID];

    const int tid = threadIdx.x;
    const int i0 = blockIdx.y * TI;
    const int j0 = blockIdx.x * TJ;

    // ---- prep-independent preamble (overlaps prep via PDL) ----
    if (tid < 16)
        cpa16(s2u(&w2s[tid * 4]), &W2[tid * 4]);
    asm volatile("cp.async.commit_group;");
    const float b2v = *b2;

    // ---- gate on prep completion (memory visible after this) ----
    asm volatile("griddepcontrol.wait;" ::: "memory");

    #pragma unroll
    for (int k = tid; k < TI * 16; k += 128) {
        int r = k >> 4, c4 = (k & 15) << 2;
        cpa16(s2u(&Us[r * ST + c4]), &g_U[i0 + r][c4]);
    }
    #pragma unroll
    for (int k = tid; k < TJ * 16; k += 128) {
        int r = k >> 4, c4 = (k & 15) << 2;
        cpa16(s2u(&Vs[r * ST + c4]), &g_V[j0 + r][c4]);
    }
    asm volatile("cp.async.commit_group;");
    asm volatile("cp.async.wait_group 0;");
    __syncthreads();

    const int ig = tid & 15;    // i = ig + 16a, a<4
    const int jg = tid >> 4;    // j = jg + 8b,  b<4

    u64 acc[4][4];
    #pragma unroll
    for (int a = 0; a < 4; a++)
        #pragma unroll
        for (int b = 0; b < 4; b++) acc[a][b] = 0ull;

    #pragma unroll 2
    for (int h = 0; h < HID; h += 4) {
        ulonglong2 w = *(const ulonglong2*)&w2s[h];
        ulonglong2 u[4], v[4];
        #pragma unroll
        for (int a = 0; a < 4; a++)
            u[a] = *(const ulonglong2*)&Us[(ig + 16 * a) * ST + h];
        #pragma unroll
        for (int b = 0; b < 4; b++)
            v[b] = *(const ulonglong2*)&Vs[(jg + 8 * b) * ST + h];
        #pragma unroll
        for (int a = 0; a < 4; a++)
            #pragma unroll
            for (int b = 0; b < 4; b++) {
                acc[a][b] = fma2(relu2(add2(u[a].x, v[b].x)), w.x, acc[a][b]);
                acc[a][b] = fma2(relu2(add2(u[a].y, v[b].y)), w.y, acc[a][b]);
            }
    }
    __syncthreads();   // done reading Us before reuse as staging

    // epilogue: horizontal add, smem stage, coalesced float4 stores
    float* outS = Us;   // 64*36 floats <= 64*68
    #pragma unroll
    for (int a = 0; a < 4; a++)
        #pragma unroll
        for (int b = 0; b < 4; b++) {
            float2 p = up2(acc[a][b]);
            outS[(ig + 16 * a) * OT + (jg + 8 * b)] = p.x + p.y + b2v;
        }
    __syncthreads();
    #pragma unroll
    for (int k = tid; k < TI * 8; k += 128) {
        int r = k >> 3, c4 = (k & 7) << 2;
        *(float4*)&out[(u64)(i0 + r) * NPIX + j0 + c4] = *(const float4*)&outS[r * OT + c4];
    }
}

// ---------------------------------------------------------------------------
extern "C" void kernel_launch(void* const* d_in, const int* in_sizes, int n_in,
                              void* d_out, int out_size) {
    // 0:h 1:w 2:q_mod 3:k_mod 4:structure_map 5:mod_embed 6:W1 7:b1 8:W2 9:b2
    const int*   qmod = (const int*)d_in[2];
    const int*   kmod = (const int*)d_in[3];
    const float* smap = (const float*)d_in[4];
    const float* memb = (const float*)d_in[5];
    const float* W1   = (const float*)d_in[6];
    const float* b1   = (const float*)d_in[7];
    const float* W2   = (const float*)d_in[8];
    const float* b2   = (const float*)d_in[9];
    float* out = (float*)d_out;

    prep_kernel<<<NPIX / 16, 128>>>(qmod, kmod, smap, memb, W1, b1);

    // main launched with Programmatic Dependent Launch (overlaps prep)
    cudaLaunchConfig_t cfg = {};
    cfg.gridDim  = dim3(NPIX / TJ, NPIX / TI);   // 50 x 25
    cfg.blockDim = dim3(128);
    cfg.stream   = 0;
    cudaLaunchAttribute attrs[1];
    attrs[0].id = cudaLaunchAttributeProgrammaticStreamSerialization;
    attrs[0].val.programmaticStreamSerializationAllowed = 1;
    cfg.attrs = attrs;
    cfg.numAttrs = 1;
    cudaLaunchKernelEx(&cfg, rpe_main_kernel, out, W2, b2);
}

// round 15
// speedup vs baseline: 1.0879x; 1.0879x over previous
#include <cuda_runtime.h>
#include <cstdint>

#define NPIX  1600
#define WIDTH 40
#define HID   64
#define TI    64
#define TJ    32
#define ST    68       // 272B rows: 16B-aligned for cp.async, conflict-free LDS.128
#define OT    36

typedef unsigned long long u64;

__device__ float g_U[NPIX][HID];
__device__ float g_V[NPIX][HID];

// ---- packed f32x2 helpers ----
static __device__ __forceinline__ u64 add2(u64 a, u64 b) {
    u64 r; asm("add.rn.f32x2 %0, %1, %2;" : "=l"(r) : "l"(a), "l"(b)); return r;
}
static __device__ __forceinline__ u64 fma2(u64 a, u64 b, u64 c) {
    u64 r; asm("fma.rn.f32x2 %0, %1, %2, %3;" : "=l"(r) : "l"(a), "l"(b), "l"(c)); return r;
}
static __device__ __forceinline__ float2 up2(u64 v) {
    float2 r; asm("mov.b64 {%0, %1}, %2;" : "=f"(r.x), "=f"(r.y) : "l"(v)); return r;
}
static __device__ __forceinline__ u64 pk2(float a, float b) {
    u64 r; asm("mov.b64 %0, {%1, %2};" : "=l"(r) : "f"(a), "f"(b)); return r;
}
static __device__ __forceinline__ u64 relu2(u64 v) {
    float2 t = up2(v);
    return pk2(fmaxf(t.x, 0.0f), fmaxf(t.y, 0.0f));
}
static __device__ __forceinline__ uint32_t s2u(const void* p) {
    return (uint32_t)__cvta_generic_to_shared(p);
}
static __device__ __forceinline__ void cpa16(uint32_t dst, const void* src) {
    asm volatile("cp.async.cg.shared.global [%0], [%1], 16;" :: "r"(dst), "l"(src));
}

// ---------------------------------------------------------------------------
// prep: 100 blocks x 128 threads, 16 pixels each. PDL: releases dependents
// at entry (their griddepcontrol.wait still blocks until prep completes).
// ---------------------------------------------------------------------------
__global__ void __launch_bounds__(128) prep_kernel(
    const int* __restrict__ qmod_p, const int* __restrict__ kmod_p,
    const float* __restrict__ smap,      // (4,1,80,80)
    const float* __restrict__ memb,      // (3,16)
    const float* __restrict__ W1,        // (36,64)
    const float* __restrict__ b1)        // (64,)
{
    asm volatile("griddepcontrol.launch_dependents;");

    __shared__ float part[16][5];
    __shared__ float s_sh[16];
    __shared__ float mv[32];
    __shared__ float Cs[HID];

    const int tid = threadIdx.x;
    const int n0  = blockIdx.x * 16;
    const float raw[4] = {0.25f, 0.75f, 0.75f, 0.25f};

    if (tid >= 64 && tid < 96) {
        int t = tid - 64;
        int m = (t < 16) ? *qmod_p : *kmod_p;
        mv[t] = memb[m * 16 + (t & 15)];
    }

    if (tid < 64) {   // one (pixel,batch) per thread, 16 taps
        const int pix = tid >> 2, bb = tid & 3;
        const int n = n0 + pix;
        const int r = n / WIDTH, c = n % WIDTH;
        const float* base = smap + bb * 6400;
        float acc = 0.f;
        #pragma unroll
        for (int ty = 0; ty < 4; ty++) {
            int iy = 2 * r - 1 + ty;
            if (iy < 0 || iy >= 80) continue;
            #pragma unroll
            for (int tx = 0; tx < 4; tx++) {
                int ix = 2 * c - 1 + tx;
                if (ix < 0 || ix >= 80) continue;
                acc += raw[ty] * raw[tx] * base[iy * 80 + ix];
            }
        }
        part[pix][bb] = acc;
    }
    __syncthreads();

    if (tid < HID) {                      // C[h]
        float cc = b1[tid];
        #pragma unroll
        for (int k = 0; k < 32; k++)
            cc += mv[k] * W1[(2 + k) * HID + tid];
        Cs[tid] = cc;
    } else if (tid < 80) {                // finalize s (edge renorm, batch mean)
        const int p = tid - 64;
        const int n = n0 + p;
        const int r = n / WIDTH, c = n % WIDTH;
        float sy = 0.f, sx = 0.f;
        #pragma unroll
        for (int q = 0; q < 4; q++) {
            int iy = 2 * r - 1 + q; if (iy >= 0 && iy < 80) sy += raw[q];
            int ix = 2 * c - 1 + q; if (ix >= 0 && ix < 80) sx += raw[q];
        }
        s_sh[p] = (part[p][0] + part[p][1] + part[p][2] + part[p][3])
                  / (sy * sx) * 0.25f;
    }
    __syncthreads();

    {   // U and V rows (h-coalesced), 8 n's per thread
        const int hh = tid & 63, ng = tid >> 6;
        const float w0  = W1[hh];
        const float w1  = W1[HID + hh];
        const float wsi = W1[34 * HID + hh];
        const float wsj = W1[35 * HID + hh];
        const float ch  = Cs[hh];
        #pragma unroll
        for (int k = 0; k < 8; k++) {
            int nn = ng * 8 + k;
            int n = n0 + nn;
            int r = n / WIDTH, c = n % WIDTH;
            float x = (float)c * (1.0f / 39.0f) - 0.5f;
            float y = (float)r * (1.0f / 39.0f) - 0.5f;
            float s = s_sh[nn];
            float xy = x * w0 + y * w1;
            g_U[n][hh] =  xy + s * wsi + ch;
            g_V[n][hh] = -xy + s * wsj;
        }
    }
}

// ---------------------------------------------------------------------------
// main: R13-proven body, h-loop unroll 2 -> 4 (larger scheduling window for
// LDS/math interleave). PDL preamble overlaps prep.
// ---------------------------------------------------------------------------
__global__ void __launch_bounds__(128, 7) rpe_main_kernel(
    float* __restrict__ out,
    const float* __restrict__ W2,    // (64,)
    const float* __restrict__ b2)    // (1,)
{
    __shared__ float Us[TI * ST];
    __shared__ float Vs[TJ * ST];
    __shared__ float w2s[HID];

    const int tid = threadIdx.x;
    const int i0 = blockIdx.y * TI;
    const int j0 = blockIdx.x * TJ;

    // prep-independent preamble (overlaps prep via PDL)
    if (tid < 16)
        cpa16(s2u(&w2s[tid * 4]), &W2[tid * 4]);
    asm volatile("cp.async.commit_group;");
    const float b2v = *b2;

    asm volatile("griddepcontrol.wait;" ::: "memory");

    #pragma unroll
    for (int k = tid; k < TI * 16; k += 128) {
        int r = k >> 4, c4 = (k & 15) << 2;
        cpa16(s2u(&Us[r * ST + c4]), &g_U[i0 + r][c4]);
    }
    #pragma unroll
    for (int k = tid; k < TJ * 16; k += 128) {
        int r = k >> 4, c4 = (k & 15) << 2;
        cpa16(s2u(&Vs[r * ST + c4]), &g_V[j0 + r][c4]);
    }
    asm volatile("cp.async.commit_group;");
    asm volatile("cp.async.wait_group 0;");
    __syncthreads();

    const int ig = tid & 15;    // i = ig + 16a, a<4
    const int jg = tid >> 4;    // j = jg + 8b,  b<4

    u64 acc[4][4];
    #pragma unroll
    for (int a = 0; a < 4; a++)
        #pragma unroll
        for (int b = 0; b < 4; b++) acc[a][b] = 0ull;

    #pragma unroll 4
    for (int h = 0; h < HID; h += 4) {
        ulonglong2 w = *(const ulonglong2*)&w2s[h];
        ulonglong2 u[4], v[4];
        #pragma unroll
        for (int a = 0; a < 4; a++)
            u[a] = *(const ulonglong2*)&Us[(ig + 16 * a) * ST + h];
        #pragma unroll
        for (int b = 0; b < 4; b++)
            v[b] = *(const ulonglong2*)&Vs[(jg + 8 * b) * ST + h];
        #pragma unroll
        for (int a = 0; a < 4; a++)
            #pragma unroll
            for (int b = 0; b < 4; b++) {
                acc[a][b] = fma2(relu2(add2(u[a].x, v[b].x)), w.x, acc[a][b]);
                acc[a][b] = fma2(relu2(add2(u[a].y, v[b].y)), w.y, acc[a][b]);
            }
    }
    __syncthreads();   // done reading Us before reuse as staging

    // epilogue: horizontal add, smem stage, coalesced float4 stores
    float* outS = Us;   // 64*36 floats <= 64*68
    #pragma unroll
    for (int a = 0; a < 4; a++)
        #pragma unroll
        for (int b = 0; b < 4; b++) {
            float2 p = up2(acc[a][b]);
            outS[(ig + 16 * a) * OT + (jg + 8 * b)] = p.x + p.y + b2v;
        }
    __syncthreads();
    #pragma unroll
    for (int k = tid; k < TI * 8; k += 128) {
        int r = k >> 3, c4 = (k & 7) << 2;
        *(float4*)&out[(u64)(i0 + r) * NPIX + j0 + c4] = *(const float4*)&outS[r * OT + c4];
    }
}

// ---------------------------------------------------------------------------
extern "C" void kernel_launch(void* const* d_in, const int* in_sizes, int n_in,
                              void* d_out, int out_size) {
    // 0:h 1:w 2:q_mod 3:k_mod 4:structure_map 5:mod_embed 6:W1 7:b1 8:W2 9:b2
    const int*   qmod = (const int*)d_in[2];
    const int*   kmod = (const int*)d_in[3];
    const float* smap = (const float*)d_in[4];
    const float* memb = (const float*)d_in[5];
    const float* W1   = (const float*)d_in[6];
    const float* b1   = (const float*)d_in[7];
    const float* W2   = (const float*)d_in[8];
    const float* b2   = (const float*)d_in[9];
    float* out = (float*)d_out;

    prep_kernel<<<NPIX / 16, 128>>>(qmod, kmod, smap, memb, W1, b1);

    cudaLaunchConfig_t cfg = {};
    cfg.gridDim  = dim3(NPIX / TJ, NPIX / TI);   // 50 x 25
    cfg.blockDim = dim3(128);
    cfg.stream   = 0;
    cudaLaunchAttribute attrs[1];
    attrs[0].id = cudaLaunchAttributeProgrammaticStreamSerialization;
    attrs[0].val.programmaticStreamSerializationAllowed = 1;
    cfg.attrs = attrs;
    cfg.numAttrs = 1;
    cudaLaunchKernelEx(&cfg, rpe_main_kernel, out, W2, b2);
}